// round 13
// baseline (speedup 1.0000x reference)
#include <cuda_runtime.h>

#define C_DIM 512
#define K_DIM 19
#define K_PAD 20                       // padded class dim (pool partial layout)
#define KH    10                       // classes per ksplit CTA
#define HW    16384
#define B_DIM 8
#define S_CHUNKS 16                    // pool chunks (1024 positions each)

typedef unsigned long long u64;

// ---- f32x2 packed helpers ----
__device__ __forceinline__ u64 pk2(float lo, float hi) {
    u64 r; asm("mov.b64 %0, {%1, %2};" : "=l"(r) : "f"(lo), "f"(hi)); return r;
}
__device__ __forceinline__ void upk2(u64 v, float& lo, float& hi) {
    asm("mov.b64 {%0, %1}, %2;" : "=f"(lo), "=f"(hi) : "l"(v));
}
__device__ __forceinline__ u64 ffma2(u64 a, u64 b, u64 c) {
    u64 d; asm("fma.rn.f32x2 %0, %1, %2, %3;" : "=l"(d) : "l"(a), "l"(b), "l"(c)); return d;
}

// Static scratch (g_pre is GONE — ksplit produces final values per stage)
__device__ float g_partial[B_DIM * S_CHUNKS * K_PAD * C_DIM];  // pooling partials (5.2MB)
__device__ float g_cf[B_DIM * K_DIM * C_DIM];                  // class features
__device__ float g_filters[B_DIM * K_DIM * C_DIM];             // dynamic filters

// ============================================================
// K1: mask = sigmoid(Wm @ x + bm) -> d_out (scratch), DIRECT write.
// grid (32 pos-tiles, 2 ksplit, 8 b), 128 thr, 4 pos/thread.
// Each CTA: 10 classes (zero-padded), FULL C=512 reduction.
// Dup'd-pair weights in smem; broadcast LDS.128 feeds 4 FFMA2.
// Manual x double-buffer -> MLP 4. Acc = 20 u64 = 40 regs.
// ============================================================
__global__ void __launch_bounds__(128, 4) k_mask(
    const float* __restrict__ x, const float* __restrict__ Wm,
    const float* __restrict__ bm, float* __restrict__ mask)
{
    __shared__ __align__(16) u64 wd[KH * C_DIM];   // 40960 B dup pairs
    int tid = threadIdx.x;
    int ksplit = blockIdx.y, b = blockIdx.z;
    int K0 = ksplit * KH;

    for (int i = tid; i < KH * C_DIM; i += 128) {
        int k = K0 + (i >> 9);
        float w = (k < K_DIM) ? Wm[k * C_DIM + (i & 511)] : 0.0f;
        wd[i] = pk2(w, w);
    }
    __syncthreads();

    int p0 = blockIdx.x * 512 + tid * 4;
    const float* xb = x + (size_t)b * C_DIM * HW + p0;

    u64 a0[KH], a1[KH];
    #pragma unroll
    for (int kh = 0; kh < KH; kh++) {
        int k = K0 + kh;
        float bv = (k < K_DIM) ? __ldg(&bm[k]) : 0.0f;
        a0[kh] = pk2(bv, bv); a1[kh] = a0[kh];
    }

    ulonglong2 xa = *(const ulonglong2*)(xb + (size_t)0 * HW);
    ulonglong2 xc = *(const ulonglong2*)(xb + (size_t)1 * HW);

    #pragma unroll 1
    for (int c = 0; c < C_DIM; c += 2) {
        int cn = (c < C_DIM - 2) ? c + 2 : c;      // clamped prefetch
        ulonglong2 xa_n = *(const ulonglong2*)(xb + (size_t)(cn + 0) * HW);
        ulonglong2 xc_n = *(const ulonglong2*)(xb + (size_t)(cn + 1) * HW);
        #pragma unroll
        for (int kh = 0; kh < KH; kh++) {
            ulonglong2 w = *(const ulonglong2*)&wd[kh * C_DIM + c];
            a0[kh] = ffma2(w.x, xa.x, a0[kh]);
            a1[kh] = ffma2(w.x, xa.y, a1[kh]);
            a0[kh] = ffma2(w.y, xc.x, a0[kh]);
            a1[kh] = ffma2(w.y, xc.y, a1[kh]);
        }
        xa = xa_n; xc = xc_n;
    }

    float* mb = mask + (size_t)b * K_DIM * HW + p0;
    #pragma unroll
    for (int kh = 0; kh < KH; kh++) {
        int k = K0 + kh;
        if (k < K_DIM) {
            float v0, v1, v2, v3;
            upk2(a0[kh], v0, v1); upk2(a1[kh], v2, v3);
            float4 s;
            s.x = 1.0f / (1.0f + __expf(-v0));
            s.y = 1.0f / (1.0f + __expf(-v1));
            s.z = 1.0f / (1.0f + __expf(-v2));
            s.w = 1.0f / (1.0f + __expf(-v3));
            *(float4*)(mb + (size_t)k * HW) = s;
        }
    }
}

// ============================================================
// K2: pooling partials. grid (2 ksplit, 16 chunks, 8 b), 256 thr.
// Each CTA: 10 classes (padded), ALL 512 channels, chunk=1024 pos.
// Mask staged as plain pair copy (sigmoid already applied by k_mask).
// Lane owns a channel-QUAD: one mask LDS.64 feeds 4 FFMA2.
// ============================================================
__global__ void __launch_bounds__(256, 2) k_pool(
    const float* __restrict__ x, const float* __restrict__ mask)
{
    __shared__ u64 m2[KH * 512];   // 40960 B
    int tid = threadIdx.x;
    int ksplit = blockIdx.x, chunk = blockIdx.y, b = blockIdx.z;
    int p0 = chunk * 1024;
    int K0 = ksplit * KH;

    for (int i = tid; i < KH * 512; i += 256) {
        int k = K0 + (i >> 9), j = i & 511;
        m2[i] = (k < K_DIM)
            ? *(const u64*)(mask + ((size_t)b * K_DIM + k) * HW + p0 + 2 * j)
            : 0ull;
    }
    __syncthreads();

    int warp = tid >> 5, lane = tid & 31;
    const float inv = 1.0f / (float)HW;
    const float* xbase = x + (size_t)b * C_DIM * HW + p0;

    for (int i = 0; i < 16; i++) {          // 8 warps x 16 = 128 quads = 512 ch
        int cbase = 4 * (warp + 8 * i);
        const float* xp0 = xbase + (size_t)(cbase + 0) * HW;
        const float* xp1 = xbase + (size_t)(cbase + 1) * HW;
        const float* xp2 = xbase + (size_t)(cbase + 2) * HW;
        const float* xp3 = xbase + (size_t)(cbase + 3) * HW;

        u64 a[4 * KH];
        #pragma unroll
        for (int j = 0; j < 4 * KH; j++) a[j] = 0ull;

        #pragma unroll 2
        for (int t = 0; t < 16; t++) {      // 16 pair-steps x 32 lanes = 512 pairs
            int idx = lane + 32 * t;
            u64 xv0 = *(const u64*)(xp0 + 2 * idx);
            u64 xv1 = *(const u64*)(xp1 + 2 * idx);
            u64 xv2 = *(const u64*)(xp2 + 2 * idx);
            u64 xv3 = *(const u64*)(xp3 + 2 * idx);
            #pragma unroll
            for (int kh = 0; kh < KH; kh++) {
                u64 m = m2[kh * 512 + idx];
                a[kh * 4 + 0] = ffma2(m, xv0, a[kh * 4 + 0]);
                a[kh * 4 + 1] = ffma2(m, xv1, a[kh * 4 + 1]);
                a[kh * 4 + 2] = ffma2(m, xv2, a[kh * 4 + 2]);
                a[kh * 4 + 3] = ffma2(m, xv3, a[kh * 4 + 3]);
            }
        }

        #pragma unroll
        for (int kh = 0; kh < KH; kh++) {
            float s[4];
            #pragma unroll
            for (int j = 0; j < 4; j++) {
                float lo, hi; upk2(a[kh * 4 + j], lo, hi); s[j] = lo + hi;
            }
            #pragma unroll
            for (int off = 16; off > 0; off >>= 1) {
                #pragma unroll
                for (int j = 0; j < 4; j++)
                    s[j] += __shfl_xor_sync(0xffffffffu, s[j], off);
            }
            if (lane == 0) {
                float* gp = &g_partial[(((size_t)b * S_CHUNKS + chunk) * K_PAD + K0 + kh) * C_DIM + cbase];
                gp[0] = s[0] * inv; gp[1] = s[1] * inv;
                gp[2] = s[2] * inv; gp[3] = s[3] * inv;
            }
        }
    }
}

// ============================================================
// K2b: reduce chunk partials -> class_feat. grid (19, 8), block 512.
// ============================================================
__global__ void __launch_bounds__(512) k_cf()
{
    int k = blockIdx.x, b = blockIdx.y;
    int c = threadIdx.x;
    const float* gp = g_partial + ((size_t)b * S_CHUNKS * K_PAD + k) * C_DIM + c;
    float sum = 0.0f;
    #pragma unroll 8
    for (int s = 0; s < S_CHUNKS; s++)
        sum += gp[(size_t)s * K_PAD * C_DIM];
    g_cf[((size_t)b * K_DIM + k) * C_DIM + c] = sum;
}

// ============================================================
// K2c: filters GEMV. grid (19, 8 osplit, 8 b) = 1216 CTAs, block 128.
// ============================================================
__global__ void __launch_bounds__(128) k_filters(
    const float* __restrict__ Wf, const float* __restrict__ bf)
{
    int k = blockIdx.x, osplit = blockIdx.y, b = blockIdx.z;
    int warp = threadIdx.x >> 5, lane = threadIdx.x & 31;

    const float4* cf4 = (const float4*)(g_cf + ((size_t)b * K_DIM + k) * C_DIM);
    float4 cfr[4];
    #pragma unroll
    for (int j = 0; j < 4; j++) cfr[j] = __ldg(&cf4[lane + 32 * j]);

    int obase = osplit * 64 + warp * 16;
    for (int g = 0; g < 4; g++) {
        int o = obase + 4 * g;
        const float4* w0 = (const float4*)(Wf + ((size_t)k * C_DIM + o + 0) * C_DIM);
        const float4* w1 = (const float4*)(Wf + ((size_t)k * C_DIM + o + 1) * C_DIM);
        const float4* w2 = (const float4*)(Wf + ((size_t)k * C_DIM + o + 2) * C_DIM);
        const float4* w3 = (const float4*)(Wf + ((size_t)k * C_DIM + o + 3) * C_DIM);

        float acc0 = 0.f, acc1 = 0.f, acc2 = 0.f, acc3 = 0.f;
        #pragma unroll
        for (int j = 0; j < 4; j++) {
            int idx = lane + 32 * j;
            float4 a = w0[idx], bb = w1[idx], cc = w2[idx], dd = w3[idx];
            float4 f = cfr[j];
            acc0 += a.x * f.x + a.y * f.y + a.z * f.z + a.w * f.w;
            acc1 += bb.x * f.x + bb.y * f.y + bb.z * f.z + bb.w * f.w;
            acc2 += cc.x * f.x + cc.y * f.y + cc.z * f.z + cc.w * f.w;
            acc3 += dd.x * f.x + dd.y * f.y + dd.z * f.z + dd.w * f.w;
        }
        #pragma unroll
        for (int off = 16; off > 0; off >>= 1) {
            acc0 += __shfl_xor_sync(0xffffffffu, acc0, off);
            acc1 += __shfl_xor_sync(0xffffffffu, acc1, off);
            acc2 += __shfl_xor_sync(0xffffffffu, acc2, off);
            acc3 += __shfl_xor_sync(0xffffffffu, acc3, off);
        }
        if (lane < 4) {
            float v = (lane == 0) ? acc0 : (lane == 1) ? acc1 : (lane == 2) ? acc2 : acc3;
            g_filters[((size_t)b * K_DIM + k) * C_DIM + o + lane] =
                v + bf[k * C_DIM + o + lane];
        }
    }
}

// ============================================================
// K3: pred = filters @ x -> d_out, DIRECT write (overwrites mask scratch).
// Same ksplit shape as k_mask; no sigmoid; bias already in filters.
// ============================================================
__global__ void __launch_bounds__(128, 4) k_pred(
    const float* __restrict__ x, float* __restrict__ out)
{
    __shared__ __align__(16) u64 wd[KH * C_DIM];
    int tid = threadIdx.x;
    int ksplit = blockIdx.y, b = blockIdx.z;
    int K0 = ksplit * KH;

    const float* fb = g_filters + (size_t)b * K_DIM * C_DIM;
    for (int i = tid; i < KH * C_DIM; i += 128) {
        int k = K0 + (i >> 9);
        float w = (k < K_DIM) ? fb[k * C_DIM + (i & 511)] : 0.0f;
        wd[i] = pk2(w, w);
    }
    __syncthreads();

    int p0 = blockIdx.x * 512 + tid * 4;
    const float* xb = x + (size_t)b * C_DIM * HW + p0;

    u64 a0[KH], a1[KH];
    #pragma unroll
    for (int kh = 0; kh < KH; kh++) { a0[kh] = 0ull; a1[kh] = 0ull; }

    ulonglong2 xa = *(const ulonglong2*)(xb + (size_t)0 * HW);
    ulonglong2 xc = *(const ulonglong2*)(xb + (size_t)1 * HW);

    #pragma unroll 1
    for (int c = 0; c < C_DIM; c += 2) {
        int cn = (c < C_DIM - 2) ? c + 2 : c;
        ulonglong2 xa_n = *(const ulonglong2*)(xb + (size_t)(cn + 0) * HW);
        ulonglong2 xc_n = *(const ulonglong2*)(xb + (size_t)(cn + 1) * HW);
        #pragma unroll
        for (int kh = 0; kh < KH; kh++) {
            ulonglong2 w = *(const ulonglong2*)&wd[kh * C_DIM + c];
            a0[kh] = ffma2(w.x, xa.x, a0[kh]);
            a1[kh] = ffma2(w.x, xa.y, a1[kh]);
            a0[kh] = ffma2(w.y, xc.x, a0[kh]);
            a1[kh] = ffma2(w.y, xc.y, a1[kh]);
        }
        xa = xa_n; xc = xc_n;
    }

    float* ob = out + (size_t)b * K_DIM * HW + p0;
    #pragma unroll
    for (int kh = 0; kh < KH; kh++) {
        int k = K0 + kh;
        if (k < K_DIM) {
            ulonglong2 v; v.x = a0[kh]; v.y = a1[kh];
            *(ulonglong2*)(ob + (size_t)k * HW) = v;
        }
    }
}

// ============================================================
extern "C" void kernel_launch(void* const* d_in, const int* in_sizes, int n_in,
                              void* d_out, int out_size)
{
    const float* x  = (const float*)d_in[0];
    const float* Wm = (const float*)d_in[1];
    const float* bm = (const float*)d_in[2];
    const float* Wf = (const float*)d_in[3];
    const float* bf = (const float*)d_in[4];
    float* out = (float*)d_out;

    // d_out doubles as mask scratch: k_mask writes it, k_pool reads it,
    // k_pred overwrites it with the final prediction.
    k_mask   <<<dim3(32, 2, B_DIM), 128>>>(x, Wm, bm, out);
    k_pool   <<<dim3(2, S_CHUNKS, B_DIM), 256>>>(x, out);
    k_cf     <<<dim3(K_DIM, B_DIM), 512>>>();
    k_filters<<<dim3(K_DIM, 8, B_DIM), 128>>>(Wf, bf);
    k_pred   <<<dim3(32, 2, B_DIM), 128>>>(x, out);
}